// round 11
// baseline (speedup 1.0000x reference)
#include <cuda_runtime.h>
#include <cstdint>

// Problem constants
#define B      32
#define T_IN   24
#define T_OUT  12
#define D      10
#define M      64
#define N      128
#define MN     (M * N)                 // 8192
#define MN8    (MN / 8)                // 1024 groups of 8 per (b,t,d=0) slice
#define IN_T_STRIDE  (D * MN)          // 81920 floats between t slices
#define IN_B_STRIDE  (T_IN * IN_T_STRIDE)
#define OUT_B_STRIDE (T_OUT * MN)
#define MU_    0.08f
#define LAM    0.92f

// 256-bit load with L2 evict_last policy (the only width this ptxas allows)
__device__ __forceinline__ void ld8_evict_last(const float* p, float v[8]) {
    uint32_t r0, r1, r2, r3, r4, r5, r6, r7;
    asm volatile(
        "ld.global.nc.L2::evict_last.v8.b32 {%0,%1,%2,%3,%4,%5,%6,%7}, [%8];"
        : "=r"(r0), "=r"(r1), "=r"(r2), "=r"(r3),
          "=r"(r4), "=r"(r5), "=r"(r6), "=r"(r7)
        : "l"(p));
    v[0] = __uint_as_float(r0); v[1] = __uint_as_float(r1);
    v[2] = __uint_as_float(r2); v[3] = __uint_as_float(r3);
    v[4] = __uint_as_float(r4); v[5] = __uint_as_float(r5);
    v[6] = __uint_as_float(r6); v[7] = __uint_as_float(r7);
}

__global__ __launch_bounds__(64)
void movavg_kernel(const float* __restrict__ x, float* __restrict__ out)
{
    const int tid = blockIdx.x * 64 + threadIdx.x;   // over B*MN/8 = 32768
    const int b   = tid >> 10;                       // / 1024
    const int mn8 = tid & 1023;

    const float* __restrict__ xin = x + (size_t)b * IN_B_STRIDE + mn8 * 8;

    // Compile-time constants
    float lam23 = 1.0f;
    #pragma unroll
    for (int i = 0; i < 23; i++) lam23 *= LAM;
    const float base = lam23 / 24.0f;
    const float Kc   = MU_ * lam23;

    float Bs[8], R[8], v23[8];
    #pragma unroll
    for (int q = 0; q < 8; q++) { Bs[q] = 0.f; R[q] = 0.f; }

    // Pass 1: stream all 24 slices (evict_last pins them in L2 for replays)
    #pragma unroll
    for (int t = 0; t < T_IN; t++) {
        float v[8];
        ld8_evict_last(xin + (size_t)t * IN_T_STRIDE, v);
        #pragma unroll
        for (int q = 0; q < 8; q++) {
            Bs[q] += v[q];
            if (t < T_IN - 1) R[q] = fmaf(LAM, R[q], MU_ * v[q]);
            else              v23[q] = v[q];
        }
    }

    float* __restrict__ yout = out + (size_t)b * OUT_B_STRIDE + mn8 * 8;

    // Epilogue: x_0..x_11 re-read (L2-hot — just fetched above)
    #pragma unroll
    for (int s = 0; s < T_OUT; s++) {
        const float4 xo0 = __ldg((const float4*)(xin + (size_t)s * IN_T_STRIDE));
        const float4 xo1 = __ldg((const float4*)(xin + (size_t)s * IN_T_STRIDE) + 1);
        const float xv[8] = {xo0.x, xo0.y, xo0.z, xo0.w, xo1.x, xo1.y, xo1.z, xo1.w};
        float p[8];
        #pragma unroll
        for (int q = 0; q < 8; q++) {
            p[q] = fmaf(base, Bs[q], R[q]);
            Bs[q] = (Bs[q] - xv[q]) + p[q];
            R[q] = fmaf(LAM, R[q], fmaf(MU_, v23[q], -Kc * xv[q]));
            v23[q] = p[q];
        }
        float4 o0, o1;
        o0.x = p[0]; o0.y = p[1]; o0.z = p[2]; o0.w = p[3];
        o1.x = p[4]; o1.y = p[5]; o1.z = p[6]; o1.w = p[7];
        float* yp = yout + (size_t)s * MN;
        *(float4*)yp       = o0;
        *((float4*)yp + 1) = o1;
    }
}

extern "C" void kernel_launch(void* const* d_in, const int* in_sizes, int n_in,
                              void* d_out, int out_size)
{
    const float* x = (const float*)d_in[0];
    float* out = (float*)d_out;
    const int total = B * MN / 8;          // 32768 threads
    movavg_kernel<<<total / 64, 64>>>(x, out);
}

// round 12
// speedup vs baseline: 1.2399x; 1.2399x over previous
#include <cuda_runtime.h>
#include <cstdint>

// Problem constants
#define B      32
#define T_IN   24
#define T_OUT  12
#define D      10
#define M      64
#define N      128
#define MN     (M * N)                 // 8192
#define IN_T_STRIDE  (D * MN)          // 81920 floats between t slices
#define IN_B_STRIDE  (T_IN * IN_T_STRIDE)
#define OUT_B_STRIDE (T_OUT * MN)
#define MU_    0.08f
#define LAM    0.92f

#define CHUNK      256                 // mn per CTA
#define NCHUNK     (MN / CHUNK)        // 32
#define THREADS    128                 // 2 series per thread (float2)
#define TILE_BYTES (T_IN * CHUNK * 4)  // 24 KB

struct __align__(128) Smem {
    float tile[T_IN][CHUNK];
    alignas(8) uint64_t mbar;
};

__device__ __forceinline__ uint32_t smem_u32(const void* p) {
    return (uint32_t)__cvta_generic_to_shared(p);
}

__global__ __launch_bounds__(THREADS)
void movavg_kernel(const float* __restrict__ x, float* __restrict__ out)
{
    __shared__ Smem sm;

    const int bid   = blockIdx.x;
    const int b     = bid >> 5;          // / NCHUNK
    const int chunk = bid & (NCHUNK - 1);
    const int tid   = threadIdx.x;

    const uint32_t mb = smem_u32(&sm.mbar);

    if (tid == 0) {
        asm volatile("mbarrier.init.shared::cta.b64 [%0], %1;" :: "r"(mb), "r"(1));
        asm volatile("mbarrier.arrive.expect_tx.shared::cta.b64 _, [%0], %1;"
                     :: "r"(mb), "r"(TILE_BYTES) : "memory");
    }
    __syncthreads();

    // 24 bulk copies of 1 KB each (contiguous per (b,t) slice), issued by 24 threads
    if (tid < T_IN) {
        const float* src = x + (size_t)(b * T_IN + tid) * IN_T_STRIDE + chunk * CHUNK;
        const uint32_t dst = smem_u32(&sm.tile[tid][0]);
        asm volatile(
            "cp.async.bulk.shared::cta.global.mbarrier::complete_tx::bytes "
            "[%0], [%1], %2, [%3];"
            :: "r"(dst), "l"(src), "r"(CHUNK * 4), "r"(mb) : "memory");
    }

    // All threads wait for the full tile
    {
        uint32_t done;
        do {
            asm volatile(
                "{\n\t.reg .pred p;\n\t"
                "mbarrier.try_wait.parity.acquire.cta.shared::cta.b64 p, [%1], %2;\n\t"
                "selp.b32 %0, 1, 0, p;\n\t}"
                : "=r"(done) : "r"(mb), "r"(0) : "memory");
        } while (!done);
    }

    // Compile-time constants
    float lam23 = 1.0f;
    #pragma unroll
    for (int i = 0; i < 23; i++) lam23 *= LAM;
    const float base = lam23 / 24.0f;
    const float Kc   = MU_ * lam23;

    const int ml = tid * 2;   // local mn pair

    // Read the 24-sample window for 2 series from smem (conflict-free)
    float va[T_IN], vb[T_IN];
    #pragma unroll
    for (int t = 0; t < T_IN; t++) {
        const float2 vv = *(const float2*)&sm.tile[t][ml];
        va[t] = vv.x; vb[t] = vv.y;
    }

    // Bs = window sum; R = truncated EMA
    float Bsa = 0.f, Ra = 0.f, Bsb = 0.f, Rb = 0.f;
    #pragma unroll
    for (int t = 0; t < T_IN; t++) {
        Bsa += va[t]; Bsb += vb[t];
        if (t < T_IN - 1) {
            Ra = fmaf(LAM, Ra, MU_ * va[t]);
            Rb = fmaf(LAM, Rb, MU_ * vb[t]);
        }
    }
    float v23a = va[T_IN - 1], v23b = vb[T_IN - 1];

    float* __restrict__ yout = out + (size_t)b * OUT_B_STRIDE + chunk * CHUNK + ml;

    #pragma unroll
    for (int s = 0; s < T_OUT; s++) {
        const float pa = fmaf(base, Bsa, Ra);
        const float pb = fmaf(base, Bsb, Rb);
        float2 o; o.x = pa; o.y = pb;
        *(float2*)(yout + (size_t)s * MN) = o;

        const float xa = va[s], xb = vb[s];
        Bsa = (Bsa - xa) + pa;
        Bsb = (Bsb - xb) + pb;
        Ra = fmaf(LAM, Ra, fmaf(MU_, v23a, -Kc * xa));
        Rb = fmaf(LAM, Rb, fmaf(MU_, v23b, -Kc * xb));
        v23a = pa; v23b = pb;
    }
}

extern "C" void kernel_launch(void* const* d_in, const int* in_sizes, int n_in,
                              void* d_out, int out_size)
{
    const float* x = (const float*)d_in[0];
    float* out = (float*)d_out;
    movavg_kernel<<<B * NCHUNK, THREADS>>>(x, out);   // 1024 CTAs
}